// round 6
// baseline (speedup 1.0000x reference)
#include <cuda_runtime.h>
#include <math.h>

#define D_MODEL 1024
#define NUM_HEADS 16
#define DEPTH 64
#define B_ 4
#define S_ 1024

// ---------------- scratch (static device globals; no allocation) -------------
__device__ float g_qc[(size_t)B_ * S_ * D_MODEL];          // 16 MB
__device__ float g_kc[(size_t)B_ * S_ * D_MODEL];          // 16 MB
__device__ float g_vc[(size_t)B_ * S_ * D_MODEL];          // 16 MB
__device__ float g_qp[(size_t)S_ * D_MODEL];               // 4 MB
__device__ float g_kp[(size_t)S_ * D_MODEL];               // 4 MB
__device__ float g_pos[(size_t)NUM_HEADS * S_ * S_];       // 64 MB
__device__ float g_scores[(size_t)B_ * NUM_HEADS * S_ * S_]; // 256 MB
__device__ float g_ctx[(size_t)B_ * S_ * D_MODEL];         // 16 MB

// ============================================================================
// Projection GEMM: out[M,1024] = X[M,1024] @ W[1024,1024] + bias
// 128x128 block, BK=8, 256 threads, 8x8 per-thread microtile.
// Grid: (1024/128, M/128)
// ============================================================================
__global__ __launch_bounds__(256, 2)
void proj_kernel(const float* __restrict__ X,
                 const float* __restrict__ W,
                 const float* __restrict__ bias,
                 float* __restrict__ out)
{
    __shared__ float As[8][128];
    __shared__ float Bs[8][128];

    const int tid = threadIdx.x;
    const int m0 = blockIdx.y * 128;
    const int n0 = blockIdx.x * 128;
    const int tx = tid & 15;
    const int ty = tid >> 4;

    const int arow = tid >> 1;          // 0..127
    const int acol = (tid & 1) << 2;    // 0 or 4
    const int brow = tid >> 5;          // 0..7
    const int bcol = (tid & 31) << 2;   // 0..124

    float acc[8][8];
#pragma unroll
    for (int i = 0; i < 8; i++)
#pragma unroll
        for (int j = 0; j < 8; j++) acc[i][j] = 0.0f;

    const float* Aptr = X + (size_t)(m0 + arow) * 1024 + acol;
    const float* Bptr = W + (size_t)brow * 1024 + n0 + bcol;

    for (int k0 = 0; k0 < 1024; k0 += 8) {
        float4 a = *(const float4*)(Aptr + k0);
        As[acol + 0][arow] = a.x;
        As[acol + 1][arow] = a.y;
        As[acol + 2][arow] = a.z;
        As[acol + 3][arow] = a.w;
        float4 bv = *(const float4*)(Bptr + (size_t)k0 * 1024);
        *(float4*)&Bs[brow][bcol] = bv;
        __syncthreads();

#pragma unroll
        for (int kk = 0; kk < 8; kk++) {
            float ra[8], rb[8];
#pragma unroll
            for (int i = 0; i < 8; i++) ra[i] = As[kk][ty * 8 + i];
#pragma unroll
            for (int j = 0; j < 8; j++) rb[j] = Bs[kk][tx * 8 + j];
#pragma unroll
            for (int i = 0; i < 8; i++)
#pragma unroll
                for (int j = 0; j < 8; j++)
                    acc[i][j] = fmaf(ra[i], rb[j], acc[i][j]);
        }
        __syncthreads();
    }

#pragma unroll
    for (int i = 0; i < 8; i++) {
        float* orow = out + (size_t)(m0 + ty * 8 + i) * 1024 + n0 + tx * 8;
#pragma unroll
        for (int j = 0; j < 8; j += 4) {
            float4 v;
            v.x = acc[i][j + 0] + bias[n0 + tx * 8 + j + 0];
            v.y = acc[i][j + 1] + bias[n0 + tx * 8 + j + 1];
            v.z = acc[i][j + 2] + bias[n0 + tx * 8 + j + 2];
            v.w = acc[i][j + 3] + bias[n0 + tx * 8 + j + 3];
            *(float4*)(orow + j) = v;
        }
    }
}

// ============================================================================
// NT GEMM core for attention scores: C[m,n] = sum_{d<64} A[m,d] * B[n,d]
// A, B row stride 1024 (head slice of [S, D_MODEL]), K = 64.
// 128x128 block, BK=8, 256 threads, 8x8 microtile.
// ============================================================================

// pos_scores = q_p @ k_p^T per head, with theta patches on row/col 0.
__global__ __launch_bounds__(256, 2)
void pos_scores_kernel(const float* __restrict__ qp,
                       const float* __restrict__ kp,
                       const float* __restrict__ tcc,
                       const float* __restrict__ tco,
                       const float* __restrict__ toc,
                       float* __restrict__ out)
{
    const int h = blockIdx.z;
    const float* A = qp + h * DEPTH;
    const float* Bm = kp + h * DEPTH;
    float* O = out + (size_t)h * S_ * S_;

    __shared__ float As[8][128];
    __shared__ float Bs[8][128];

    const int tid = threadIdx.x;
    const int m0 = blockIdx.y * 128;
    const int n0 = blockIdx.x * 128;
    const int tx = tid & 15;
    const int ty = tid >> 4;
    const int arow = tid >> 1;
    const int acol = (tid & 1) << 2;

    float acc[8][8];
#pragma unroll
    for (int i = 0; i < 8; i++)
#pragma unroll
        for (int j = 0; j < 8; j++) acc[i][j] = 0.0f;

    for (int k0 = 0; k0 < 64; k0 += 8) {
        float4 a = *(const float4*)(A + (size_t)(m0 + arow) * 1024 + k0 + acol);
        As[acol + 0][arow] = a.x;
        As[acol + 1][arow] = a.y;
        As[acol + 2][arow] = a.z;
        As[acol + 3][arow] = a.w;
        float4 b = *(const float4*)(Bm + (size_t)(n0 + arow) * 1024 + k0 + acol);
        Bs[acol + 0][arow] = b.x;
        Bs[acol + 1][arow] = b.y;
        Bs[acol + 2][arow] = b.z;
        Bs[acol + 3][arow] = b.w;
        __syncthreads();

#pragma unroll
        for (int kk = 0; kk < 8; kk++) {
            float ra[8], rb[8];
#pragma unroll
            for (int i = 0; i < 8; i++) ra[i] = As[kk][ty * 8 + i];
#pragma unroll
            for (int j = 0; j < 8; j++) rb[j] = Bs[kk][tx * 8 + j];
#pragma unroll
            for (int i = 0; i < 8; i++)
#pragma unroll
                for (int j = 0; j < 8; j++)
                    acc[i][j] = fmaf(ra[i], rb[j], acc[i][j]);
        }
        __syncthreads();
    }

    const float thcc = tcc[h], thco = tco[h], thoc = toc[h];
#pragma unroll
    for (int i = 0; i < 8; i++) {
        const int m = m0 + ty * 8 + i;
#pragma unroll
        for (int j = 0; j < 8; j++) {
            const int n = n0 + tx * 8 + j;
            float v = acc[i][j];
            if (m == 0) v = (n == 0) ? thcc : thco;
            else if (n == 0) v = thoc;
            O[(size_t)m * S_ + n] = v;
        }
    }
}

// content scores + pos add + 1/sqrt(depth) scale
__global__ __launch_bounds__(256, 2)
void content_scores_kernel(const float* __restrict__ qc,
                           const float* __restrict__ kc,
                           const float* __restrict__ pos,
                           float* __restrict__ out)
{
    const int bh = blockIdx.z;            // 0..63
    const int b = bh >> 4;
    const int h = bh & 15;
    const float* A = qc + (size_t)b * S_ * D_MODEL + h * DEPTH;
    const float* Bm = kc + (size_t)b * S_ * D_MODEL + h * DEPTH;
    const float* P = pos + (size_t)h * S_ * S_;
    float* O = out + (size_t)bh * S_ * S_;

    __shared__ float As[8][128];
    __shared__ float Bs[8][128];

    const int tid = threadIdx.x;
    const int m0 = blockIdx.y * 128;
    const int n0 = blockIdx.x * 128;
    const int tx = tid & 15;
    const int ty = tid >> 4;
    const int arow = tid >> 1;
    const int acol = (tid & 1) << 2;

    float acc[8][8];
#pragma unroll
    for (int i = 0; i < 8; i++)
#pragma unroll
        for (int j = 0; j < 8; j++) acc[i][j] = 0.0f;

    for (int k0 = 0; k0 < 64; k0 += 8) {
        float4 a = *(const float4*)(A + (size_t)(m0 + arow) * 1024 + k0 + acol);
        As[acol + 0][arow] = a.x;
        As[acol + 1][arow] = a.y;
        As[acol + 2][arow] = a.z;
        As[acol + 3][arow] = a.w;
        float4 b = *(const float4*)(Bm + (size_t)(n0 + arow) * 1024 + k0 + acol);
        Bs[acol + 0][arow] = b.x;
        Bs[acol + 1][arow] = b.y;
        Bs[acol + 2][arow] = b.z;
        Bs[acol + 3][arow] = b.w;
        __syncthreads();

#pragma unroll
        for (int kk = 0; kk < 8; kk++) {
            float ra[8], rb[8];
#pragma unroll
            for (int i = 0; i < 8; i++) ra[i] = As[kk][ty * 8 + i];
#pragma unroll
            for (int j = 0; j < 8; j++) rb[j] = Bs[kk][tx * 8 + j];
#pragma unroll
            for (int i = 0; i < 8; i++)
#pragma unroll
                for (int j = 0; j < 8; j++)
                    acc[i][j] = fmaf(ra[i], rb[j], acc[i][j]);
        }
        __syncthreads();
    }

    const float scale = 0.125f;  // 1/sqrt(64)
#pragma unroll
    for (int i = 0; i < 8; i++) {
        const size_t m = (size_t)(m0 + ty * 8 + i);
#pragma unroll
        for (int j = 0; j < 8; j += 4) {
            const int n = n0 + tx * 8 + j;
            float4 p = *(const float4*)(P + m * S_ + n);
            float4 v;
            v.x = (acc[i][j + 0] + p.x) * scale;
            v.y = (acc[i][j + 1] + p.y) * scale;
            v.z = (acc[i][j + 2] + p.z) * scale;
            v.w = (acc[i][j + 3] + p.w) * scale;
            *(float4*)(O + m * S_ + n) = v;
        }
    }
}

// ============================================================================
// Row softmax over 1024 elements, in place. One block (128 threads) per row.
// ============================================================================
__global__ __launch_bounds__(128)
void softmax_kernel(float* __restrict__ s)
{
    const size_t row = blockIdx.x;
    float* p = s + row * 1024;
    const int t = threadIdx.x;
    const int lane = t & 31;
    const int wid = t >> 5;
    __shared__ float sh[4];

    float4 a = *(float4*)(p + t * 8);
    float4 c = *(float4*)(p + t * 8 + 4);

    float mx = fmaxf(fmaxf(fmaxf(a.x, a.y), fmaxf(a.z, a.w)),
                     fmaxf(fmaxf(c.x, c.y), fmaxf(c.z, c.w)));
#pragma unroll
    for (int o = 16; o > 0; o >>= 1) mx = fmaxf(mx, __shfl_xor_sync(0xffffffffu, mx, o));
    if (lane == 0) sh[wid] = mx;
    __syncthreads();
    mx = fmaxf(fmaxf(sh[0], sh[1]), fmaxf(sh[2], sh[3]));

    a.x = expf(a.x - mx); a.y = expf(a.y - mx); a.z = expf(a.z - mx); a.w = expf(a.w - mx);
    c.x = expf(c.x - mx); c.y = expf(c.y - mx); c.z = expf(c.z - mx); c.w = expf(c.w - mx);

    float sum = a.x + a.y + a.z + a.w + c.x + c.y + c.z + c.w;
#pragma unroll
    for (int o = 16; o > 0; o >>= 1) sum += __shfl_xor_sync(0xffffffffu, sum, o);
    __syncthreads();
    if (lane == 0) sh[wid] = sum;
    __syncthreads();
    sum = sh[0] + sh[1] + sh[2] + sh[3];

    const float inv = 1.0f / sum;
    a.x *= inv; a.y *= inv; a.z *= inv; a.w *= inv;
    c.x *= inv; c.y *= inv; c.z *= inv; c.w *= inv;
    *(float4*)(p + t * 8) = a;
    *(float4*)(p + t * 8 + 4) = c;
}

// ============================================================================
// attn @ V per (b,h): C[1024,64] = A[1024,1024] @ V[1024,64 (stride 1024)]
// 64x64 block, BK=16, 256 threads, 4x4 microtile. Writes into merged
// [B,S,D_MODEL] layout at column offset h*64.
// Grid: (1, 1024/64, 64)
// ============================================================================
__global__ __launch_bounds__(256, 2)
void av_kernel(const float* __restrict__ attn,
               const float* __restrict__ vc,
               float* __restrict__ ctx)
{
    const int bh = blockIdx.z;
    const int b = bh >> 4;
    const int h = bh & 15;
    const float* A = attn + (size_t)bh * S_ * S_;
    const float* Bv = vc + (size_t)b * S_ * D_MODEL + h * DEPTH;
    float* O = ctx + (size_t)b * S_ * D_MODEL + h * DEPTH;

    __shared__ float As[16][64];
    __shared__ float Bs[16][64];

    const int tid = threadIdx.x;
    const int m0 = blockIdx.y * 64;
    const int tx = tid & 15;           // 0..15 -> cols
    const int ty = tid >> 4;           // 0..15 -> rows
    const int arow = tid >> 2;         // 0..63
    const int acol = (tid & 3) << 2;   // 0,4,8,12
    const int brow = tid >> 4;         // 0..15
    const int bcol = (tid & 15) << 2;  // 0..60

    float acc[4][4];
#pragma unroll
    for (int i = 0; i < 4; i++)
#pragma unroll
        for (int j = 0; j < 4; j++) acc[i][j] = 0.0f;

    for (int k0 = 0; k0 < 1024; k0 += 16) {
        float4 a = *(const float4*)(A + (size_t)(m0 + arow) * S_ + k0 + acol);
        As[acol + 0][arow] = a.x;
        As[acol + 1][arow] = a.y;
        As[acol + 2][arow] = a.z;
        As[acol + 3][arow] = a.w;
        float4 bv4 = *(const float4*)(Bv + (size_t)(k0 + brow) * D_MODEL + bcol);
        *(float4*)&Bs[brow][bcol] = bv4;
        __syncthreads();

#pragma unroll
        for (int kk = 0; kk < 16; kk++) {
            float ra[4], rb[4];
#pragma unroll
            for (int i = 0; i < 4; i++) ra[i] = As[kk][ty * 4 + i];
#pragma unroll
            for (int j = 0; j < 4; j++) rb[j] = Bs[kk][tx * 4 + j];
#pragma unroll
            for (int i = 0; i < 4; i++)
#pragma unroll
                for (int j = 0; j < 4; j++)
                    acc[i][j] = fmaf(ra[i], rb[j], acc[i][j]);
        }
        __syncthreads();
    }

#pragma unroll
    for (int i = 0; i < 4; i++) {
        float4 vv;
        vv.x = acc[i][0]; vv.y = acc[i][1]; vv.z = acc[i][2]; vv.w = acc[i][3];
        *(float4*)(O + (size_t)(m0 + ty * 4 + i) * D_MODEL + tx * 4) = vv;
    }
}

// ============================================================================
// kernel_launch: graph-capturable sequence on the default stream.
// Input order (metadata): q,k,v,Wq,bq,Wk,bk,Wv,bv,Uq,buq,Uk,buk,pos_table,
//                         theta_cc,theta_co,theta_oc,Wo,bo
// ============================================================================
extern "C" void kernel_launch(void* const* d_in, const int* in_sizes, int n_in,
                              void* d_out, int out_size)
{
    (void)in_sizes; (void)n_in; (void)out_size;

    const float* q   = (const float*)d_in[0];
    const float* k   = (const float*)d_in[1];
    const float* v   = (const float*)d_in[2];
    const float* Wq  = (const float*)d_in[3];
    const float* bq  = (const float*)d_in[4];
    const float* Wk  = (const float*)d_in[5];
    const float* bk  = (const float*)d_in[6];
    const float* Wv  = (const float*)d_in[7];
    const float* bv  = (const float*)d_in[8];
    const float* Uq  = (const float*)d_in[9];
    const float* buq = (const float*)d_in[10];
    const float* Uk  = (const float*)d_in[11];
    const float* buk = (const float*)d_in[12];
    const float* pt  = (const float*)d_in[13];  // pos_table [5000,1024]; rows 0..1023 used
    const float* tcc = (const float*)d_in[14];
    const float* tco = (const float*)d_in[15];
    const float* toc = (const float*)d_in[16];
    const float* Wo  = (const float*)d_in[17];
    const float* bo  = (const float*)d_in[18];
    float* out = (float*)d_out;

    float *qc, *kc, *vc, *qp, *kp, *pos, *scores, *ctx;
    cudaGetSymbolAddress((void**)&qc, g_qc);
    cudaGetSymbolAddress((void**)&kc, g_kc);
    cudaGetSymbolAddress((void**)&vc, g_vc);
    cudaGetSymbolAddress((void**)&qp, g_qp);
    cudaGetSymbolAddress((void**)&kp, g_kp);
    cudaGetSymbolAddress((void**)&pos, g_pos);
    cudaGetSymbolAddress((void**)&scores, g_scores);
    cudaGetSymbolAddress((void**)&ctx, g_ctx);

    const dim3 blk(256);

    // Content projections: [4096,1024] @ [1024,1024]
    proj_kernel<<<dim3(8, 32), blk>>>(q, Wq, bq, qc);
    proj_kernel<<<dim3(8, 32), blk>>>(k, Wk, bk, kc);
    proj_kernel<<<dim3(8, 32), blk>>>(v, Wv, bv, vc);

    // Positional projections: [1024,1024] @ [1024,1024]
    proj_kernel<<<dim3(8, 8), blk>>>(pt, Uq, buq, qp);
    proj_kernel<<<dim3(8, 8), blk>>>(pt, Uk, buk, kp);

    // pos scores per head (with theta patches)
    pos_scores_kernel<<<dim3(8, 8, NUM_HEADS), blk>>>(qp, kp, tcc, tco, toc, pos);

    // content scores + pos + scale
    content_scores_kernel<<<dim3(8, 8, B_ * NUM_HEADS), blk>>>(qc, kc, pos, scores);

    // softmax (in place)
    softmax_kernel<<<B_ * NUM_HEADS * S_, 128>>>(scores);

    // attn @ V -> merged context [B,S,D_MODEL]
    av_kernel<<<dim3(1, S_ / 64, B_ * NUM_HEADS), blk>>>(scores, vc, ctx);

    // output projection -> d_out
    proj_kernel<<<dim3(8, 32), blk>>>(ctx, Wo, bo, out);
}

// round 10
// speedup vs baseline: 1.9834x; 1.9834x over previous
#include <cuda_runtime.h>
#include <cuda_bf16.h>
#include <math.h>
#include <stdint.h>

#define D_MODEL 1024
#define NUM_HEADS 16
#define DEPTH 64
#define B_ 4
#define S_ 1024

// ---------------- scratch (static device globals; no allocation) -------------
__device__ float g_qc[(size_t)B_ * S_ * D_MODEL];            // 16 MB
__device__ float g_kc[(size_t)B_ * S_ * D_MODEL];            // 16 MB
__device__ float g_vc[(size_t)B_ * S_ * D_MODEL];            // 16 MB
__device__ float g_qp[(size_t)S_ * D_MODEL];                 // 4 MB
__device__ float g_kp[(size_t)S_ * D_MODEL];                 // 4 MB
__device__ float g_pos[(size_t)NUM_HEADS * S_ * S_];         // 64 MB
__device__ float g_scores[(size_t)B_ * NUM_HEADS * S_ * S_]; // 256 MB
__device__ float g_ctx[(size_t)B_ * S_ * D_MODEL];           // 16 MB
__device__ float g_wt[(size_t)6 * D_MODEL * D_MODEL];        // 24 MB (W^T x6)
__device__ float g_vt[(size_t)B_ * NUM_HEADS * DEPTH * S_];  // 16 MB (V^T per head)

// ============================================================================
// mma.sync helpers (sm_80+ baseline features; work on plain sm_103 target)
// ============================================================================
__device__ __forceinline__ uint32_t smem_u32(const void* p) {
    uint32_t a;
    asm("{ .reg .u64 t; cvta.to.shared.u64 t, %1; cvt.u32.u64 %0, t; }" : "=r"(a) : "l"(p));
    return a;
}

__device__ __forceinline__ void ldsm4(uint32_t& r0, uint32_t& r1, uint32_t& r2,
                                      uint32_t& r3, uint32_t addr) {
    asm volatile("ldmatrix.sync.aligned.m8n8.x4.shared.b16 {%0,%1,%2,%3}, [%4];"
                 : "=r"(r0), "=r"(r1), "=r"(r2), "=r"(r3) : "r"(addr));
}

__device__ __forceinline__ void mma16816(float* c, const uint32_t* a, const uint32_t* b) {
    asm volatile("mma.sync.aligned.m16n8k16.row.col.f32.bf16.bf16.f32 "
                 "{%0,%1,%2,%3}, {%4,%5,%6,%7}, {%8,%9}, {%0,%1,%2,%3};"
                 : "+f"(c[0]), "+f"(c[1]), "+f"(c[2]), "+f"(c[3])
                 : "r"(a[0]), "r"(a[1]), "r"(a[2]), "r"(a[3]), "r"(b[0]), "r"(b[1]));
}

// fp32 -> (bf16 hi, bf16 lo) pair, packed
__device__ __forceinline__ void split_pair(float x, float y, uint32_t& hi, uint32_t& lo) {
    __nv_bfloat162 h = __floats2bfloat162_rn(x, y);
    float hx = __bfloat162float(h.x);
    float hy = __bfloat162float(h.y);
    __nv_bfloat162 l = __floats2bfloat162_rn(x - hx, y - hy);
    hi = *reinterpret_cast<uint32_t*>(&h);
    lo = *reinterpret_cast<uint32_t*>(&l);
}

__device__ __forceinline__ void split_store(char* sH, char* sL, uint32_t off, float4 v) {
    uint32_t h0, l0, h1, l1;
    split_pair(v.x, v.y, h0, l0);
    split_pair(v.z, v.w, h1, l1);
    *(uint2*)(sH + off) = make_uint2(h0, h1);
    *(uint2*)(sL + off) = make_uint2(l0, l1);
}

// ============================================================================
// Shared bf16x3 NT GEMM core: acc[128, BN] += A[128, K] * Bt[BN, K]^T
// A, Bt fp32 row-major (K contiguous), split hi/lo to bf16 in SMEM.
// 256 threads. BN=128: 8 warps as 2(M)x4(N), warp tile 64x32 (MT=4).
// BN=64:  8 warps as 4(M)x2(N), warp tile 32x32 (MT=2). NT=4 always.
// SMEM rows padded to 24 bf16 (48B) -> conflict-free ldmatrix.
// ============================================================================
template <int BN>
__device__ __forceinline__ void gemm_bf16x3(
    const float* __restrict__ A, int lda, int m0,
    const float* __restrict__ Bt, int ldb, int n0,
    int kIters, float* __restrict__ acc)
{
    constexpr int NWN = BN / 32;      // warps along N
    constexpr int NWM = 8 / NWN;      // warps along M
    constexpr int WROWS = 128 / NWM;  // rows per warp
    constexpr int MT = WROWS / 16;    // m16 tiles per warp

    __shared__ __align__(16) __nv_bfloat16 sAh[128][24];
    __shared__ __align__(16) __nv_bfloat16 sAl[128][24];
    __shared__ __align__(16) __nv_bfloat16 sBh[BN][24];
    __shared__ __align__(16) __nv_bfloat16 sBl[BN][24];

    const int tid = threadIdx.x;
    const int lane = tid & 31;
    const int wid = tid >> 5;
    const int warp_n = wid % NWN;
    const int warp_m = wid / NWN;

    // global-load geometry: thread handles rows (tid>>2) and (tid>>2)+64,
    // float4 column (tid&3) within the 16-wide k-chunk
    const int row0 = tid >> 2;
    const int c0 = tid & 3;

    const float* ApA = A + (size_t)(m0 + row0) * lda + c0 * 4;
    const float* ApB = ApA + (size_t)64 * lda;
    const float* BpA = Bt + (size_t)(n0 + row0) * ldb + c0 * 4;
    const float* BpB = BpA + (size_t)64 * ldb;

    const uint32_t stA = (uint32_t)row0 * 48u + (uint32_t)c0 * 8u;
    const uint32_t stB = stA + 64u * 48u;

    const uint32_t baseAh = smem_u32(sAh);
    const uint32_t baseAl = smem_u32(sAl);
    const uint32_t baseBh = smem_u32(sBh);
    const uint32_t baseBl = smem_u32(sBl);

    // ldmatrix lane offsets
    const uint32_t a_off =
        (uint32_t)((warp_m * WROWS + (lane & 7) + ((lane >> 3) & 1) * 8) * 48 +
                   (lane >> 4) * 16);
    const uint32_t b_off =
        (uint32_t)((warp_n * 32 + (lane & 7) + ((lane >> 4) & 1) * 8) * 48 +
                   ((lane >> 3) & 1) * 16);

    float4 ra0 = *(const float4*)ApA;
    float4 ra1 = *(const float4*)ApB;
    float4 rb0 = *(const float4*)BpA;
    float4 rb1 = make_float4(0.f, 0.f, 0.f, 0.f);
    if (BN == 128) rb1 = *(const float4*)BpB;

    for (int it = 0; it < kIters; ++it) {
        __syncthreads();  // previous iteration's SMEM reads complete
        split_store((char*)sAh, (char*)sAl, stA, ra0);
        split_store((char*)sAh, (char*)sAl, stB, ra1);
        split_store((char*)sBh, (char*)sBl, stA, rb0);
        if (BN == 128) split_store((char*)sBh, (char*)sBl, stB, rb1);
        __syncthreads();  // tiles ready

        if (it + 1 < kIters) {
            const int ko = (it + 1) * 16;
            ra0 = *(const float4*)(ApA + ko);
            ra1 = *(const float4*)(ApB + ko);
            rb0 = *(const float4*)(BpA + ko);
            if (BN == 128) rb1 = *(const float4*)(BpB + ko);
        }

        uint32_t ah[MT][4], bh[4][2];
#pragma unroll
        for (int mt = 0; mt < MT; mt++)
            ldsm4(ah[mt][0], ah[mt][1], ah[mt][2], ah[mt][3],
                  baseAh + a_off + (uint32_t)(mt * 16 * 48));
#pragma unroll
        for (int p = 0; p < 2; p++) {
            uint32_t t0, t1, t2, t3;
            ldsm4(t0, t1, t2, t3, baseBh + b_off + (uint32_t)(p * 16 * 48));
            bh[2 * p][0] = t0; bh[2 * p][1] = t1;
            bh[2 * p + 1][0] = t2; bh[2 * p + 1][1] = t3;
        }
        // pass 1: hi x hi
#pragma unroll
        for (int mt = 0; mt < MT; mt++)
#pragma unroll
            for (int nt = 0; nt < 4; nt++)
                mma16816(acc + (mt * 4 + nt) * 4, ah[mt], bh[nt]);

        // pass 2: hi x lo
        uint32_t bl[4][2];
#pragma unroll
        for (int p = 0; p < 2; p++) {
            uint32_t t0, t1, t2, t3;
            ldsm4(t0, t1, t2, t3, baseBl + b_off + (uint32_t)(p * 16 * 48));
            bl[2 * p][0] = t0; bl[2 * p][1] = t1;
            bl[2 * p + 1][0] = t2; bl[2 * p + 1][1] = t3;
        }
#pragma unroll
        for (int mt = 0; mt < MT; mt++)
#pragma unroll
            for (int nt = 0; nt < 4; nt++)
                mma16816(acc + (mt * 4 + nt) * 4, ah[mt], bl[nt]);

        // pass 3: lo x hi
        uint32_t al[MT][4];
#pragma unroll
        for (int mt = 0; mt < MT; mt++)
            ldsm4(al[mt][0], al[mt][1], al[mt][2], al[mt][3],
                  baseAl + a_off + (uint32_t)(mt * 16 * 48));
#pragma unroll
        for (int mt = 0; mt < MT; mt++)
#pragma unroll
            for (int nt = 0; nt < 4; nt++)
                mma16816(acc + (mt * 4 + nt) * 4, al[mt], bh[nt]);
    }
}

// ============================================================================
// Projection: out[M,1024] = X @ W + bias  (Wt = W^T provided)
// ============================================================================
__global__ __launch_bounds__(256, 1)
void proj_mma(const float* __restrict__ X, const float* __restrict__ Wt,
              const float* __restrict__ bias, float* __restrict__ out)
{
    float acc[64];
#pragma unroll
    for (int i = 0; i < 64; i++) acc[i] = 0.0f;
    const int m0 = blockIdx.y * 128, n0 = blockIdx.x * 128;
    gemm_bf16x3<128>(X, 1024, m0, Wt, 1024, n0, 64, acc);

    const int lane = threadIdx.x & 31, wid = threadIdx.x >> 5;
    const int warp_n = wid & 3, warp_m = wid >> 2;
    const int rbase = m0 + warp_m * 64 + (lane >> 2);
    const int cbase = n0 + warp_n * 32 + (lane & 3) * 2;
#pragma unroll
    for (int mt = 0; mt < 4; mt++)
#pragma unroll
        for (int nt = 0; nt < 4; nt++) {
            const float* a = acc + (mt * 4 + nt) * 4;
            const int r = rbase + mt * 16;
            const int c = cbase + nt * 8;
            float2 b2 = *(const float2*)(bias + c);
            *(float2*)(out + (size_t)r * 1024 + c) = make_float2(a[0] + b2.x, a[1] + b2.y);
            *(float2*)(out + (size_t)(r + 8) * 1024 + c) = make_float2(a[2] + b2.x, a[3] + b2.y);
        }
}

// ============================================================================
// pos scores: pos[h] = q_p @ k_p^T with theta patches; K=64
// ============================================================================
__global__ __launch_bounds__(256, 1)
void pos_mma(const float* __restrict__ qp, const float* __restrict__ kp,
             const float* __restrict__ tcc, const float* __restrict__ tco,
             const float* __restrict__ toc, float* __restrict__ pos)
{
    const int h = blockIdx.z;
    float acc[64];
#pragma unroll
    for (int i = 0; i < 64; i++) acc[i] = 0.0f;
    const int m0 = blockIdx.y * 128, n0 = blockIdx.x * 128;
    gemm_bf16x3<128>(qp + h * DEPTH, 1024, m0, kp + h * DEPTH, 1024, n0, 4, acc);

    const float thcc = tcc[h], thco = tco[h], thoc = toc[h];
    float* O = pos + (size_t)h * S_ * S_;

    const int lane = threadIdx.x & 31, wid = threadIdx.x >> 5;
    const int warp_n = wid & 3, warp_m = wid >> 2;
    const int rbase = m0 + warp_m * 64 + (lane >> 2);
    const int cbase = n0 + warp_n * 32 + (lane & 3) * 2;
#pragma unroll
    for (int mt = 0; mt < 4; mt++)
#pragma unroll
        for (int nt = 0; nt < 4; nt++) {
            const float* a = acc + (mt * 4 + nt) * 4;
            const int r = rbase + mt * 16;
            const int c = cbase + nt * 8;
            float v0 = a[0], v1 = a[1], v2 = a[2], v3 = a[3];
            if (r == 0) { v0 = (c == 0) ? thcc : thco; v1 = thco; }
            else if (c == 0) v0 = thoc;
            if (c == 0) v2 = thoc;  // row r+8 >= 8, never row 0
            *(float2*)(O + (size_t)r * 1024 + c) = make_float2(v0, v1);
            *(float2*)(O + (size_t)(r + 8) * 1024 + c) = make_float2(v2, v3);
        }
}

// ============================================================================
// content scores: scores[bh] = (q_c @ k_c^T + pos[h]) / 8 ; K=64
// ============================================================================
__global__ __launch_bounds__(256, 1)
void content_mma(const float* __restrict__ qc, const float* __restrict__ kc,
                 const float* __restrict__ pos, float* __restrict__ scores)
{
    const int bh = blockIdx.z;
    const int b = bh >> 4, h = bh & 15;
    float acc[64];
#pragma unroll
    for (int i = 0; i < 64; i++) acc[i] = 0.0f;
    const int m0 = blockIdx.y * 128, n0 = blockIdx.x * 128;
    gemm_bf16x3<128>(qc + (size_t)b * S_ * D_MODEL + h * DEPTH, 1024, m0,
                     kc + (size_t)b * S_ * D_MODEL + h * DEPTH, 1024, n0, 4, acc);

    const float* P = pos + (size_t)h * S_ * S_;
    float* O = scores + (size_t)bh * S_ * S_;
    const float scale = 0.125f;

    const int lane = threadIdx.x & 31, wid = threadIdx.x >> 5;
    const int warp_n = wid & 3, warp_m = wid >> 2;
    const int rbase = m0 + warp_m * 64 + (lane >> 2);
    const int cbase = n0 + warp_n * 32 + (lane & 3) * 2;
#pragma unroll
    for (int mt = 0; mt < 4; mt++)
#pragma unroll
        for (int nt = 0; nt < 4; nt++) {
            const float* a = acc + (mt * 4 + nt) * 4;
            const int r = rbase + mt * 16;
            const int c = cbase + nt * 8;
            float2 p0 = *(const float2*)(P + (size_t)r * 1024 + c);
            float2 p1 = *(const float2*)(P + (size_t)(r + 8) * 1024 + c);
            *(float2*)(O + (size_t)r * 1024 + c) =
                make_float2((a[0] + p0.x) * scale, (a[1] + p0.y) * scale);
            *(float2*)(O + (size_t)(r + 8) * 1024 + c) =
                make_float2((a[2] + p1.x) * scale, (a[3] + p1.y) * scale);
        }
}

// ============================================================================
// attn @ V: ctx[b, m, h*64+c] = sum_k attn[bh][m][k] * Vt[bh][c][k]; K=1024
// BN = 64 (DEPTH)
// ============================================================================
__global__ __launch_bounds__(256, 1)
void av_mma(const float* __restrict__ scores, const float* __restrict__ vt,
            float* __restrict__ ctx)
{
    const int bh = blockIdx.z;
    const int b = bh >> 4, h = bh & 15;
    float acc[32];
#pragma unroll
    for (int i = 0; i < 32; i++) acc[i] = 0.0f;
    const int m0 = blockIdx.y * 128;
    gemm_bf16x3<64>(scores + (size_t)bh * S_ * S_, 1024, m0,
                    vt + (size_t)bh * DEPTH * S_, 1024, 0, 64, acc);

    float* O = ctx + (size_t)b * S_ * D_MODEL + h * DEPTH;
    const int lane = threadIdx.x & 31, wid = threadIdx.x >> 5;
    const int warp_n = wid & 1, warp_m = wid >> 1;
    const int rbase = m0 + warp_m * 32 + (lane >> 2);
    const int cbase = warp_n * 32 + (lane & 3) * 2;
#pragma unroll
    for (int mt = 0; mt < 2; mt++)
#pragma unroll
        for (int nt = 0; nt < 4; nt++) {
            const float* a = acc + (mt * 4 + nt) * 4;
            const int r = rbase + mt * 16;
            const int c = cbase + nt * 8;
            *(float2*)(O + (size_t)r * 1024 + c) = make_float2(a[0], a[1]);
            *(float2*)(O + (size_t)(r + 8) * 1024 + c) = make_float2(a[2], a[3]);
        }
}

// ============================================================================
// 1024x1024 transpose (weights)
// ============================================================================
__global__ __launch_bounds__(256)
void transpose1024(const float* __restrict__ in, float* __restrict__ out) {
    __shared__ float t[32][33];
    const int bx = blockIdx.x * 32, by = blockIdx.y * 32;
    const int txx = threadIdx.x, tyy = threadIdx.y;
#pragma unroll
    for (int i = tyy; i < 32; i += 8)
        t[i][txx] = in[(size_t)(by + i) * 1024 + bx + txx];
    __syncthreads();
#pragma unroll
    for (int i = tyy; i < 32; i += 8)
        out[(size_t)(bx + i) * 1024 + by + txx] = t[txx][i];
}

// vt[bh][d][s] = vc[b][s][h*64+d]   grid: (S/32, DEPTH/32, B*H), block (32,8)
__global__ __launch_bounds__(256)
void transpose_v(const float* __restrict__ vc, float* __restrict__ vt) {
    __shared__ float t[32][33];
    const int bh = blockIdx.z;
    const int b = bh >> 4, h = bh & 15;
    const int s0 = blockIdx.x * 32, d0 = blockIdx.y * 32;
    const int txx = threadIdx.x, tyy = threadIdx.y;
#pragma unroll
    for (int i = tyy; i < 32; i += 8)
        t[i][txx] = vc[((size_t)b * S_ + s0 + i) * D_MODEL + h * DEPTH + d0 + txx];
    __syncthreads();
#pragma unroll
    for (int i = tyy; i < 32; i += 8)
        vt[(size_t)bh * DEPTH * S_ + (size_t)(d0 + i) * S_ + s0 + txx] = t[txx][i];
}

// ============================================================================
// Row softmax over 1024 elements, in place
// ============================================================================
__global__ __launch_bounds__(128)
void softmax_kernel(float* __restrict__ s)
{
    const size_t row = blockIdx.x;
    float* p = s + row * 1024;
    const int t = threadIdx.x;
    const int lane = t & 31;
    const int wid = t >> 5;
    __shared__ float sh[4];

    float4 a = *(float4*)(p + t * 8);
    float4 c = *(float4*)(p + t * 8 + 4);

    float mx = fmaxf(fmaxf(fmaxf(a.x, a.y), fmaxf(a.z, a.w)),
                     fmaxf(fmaxf(c.x, c.y), fmaxf(c.z, c.w)));
#pragma unroll
    for (int o = 16; o > 0; o >>= 1) mx = fmaxf(mx, __shfl_xor_sync(0xffffffffu, mx, o));
    if (lane == 0) sh[wid] = mx;
    __syncthreads();
    mx = fmaxf(fmaxf(sh[0], sh[1]), fmaxf(sh[2], sh[3]));

    a.x = expf(a.x - mx); a.y = expf(a.y - mx); a.z = expf(a.z - mx); a.w = expf(a.w - mx);
    c.x = expf(c.x - mx); c.y = expf(c.y - mx); c.z = expf(c.z - mx); c.w = expf(c.w - mx);

    float sum = a.x + a.y + a.z + a.w + c.x + c.y + c.z + c.w;
#pragma unroll
    for (int o = 16; o > 0; o >>= 1) sum += __shfl_xor_sync(0xffffffffu, sum, o);
    __syncthreads();
    if (lane == 0) sh[wid] = sum;
    __syncthreads();
    sum = sh[0] + sh[1] + sh[2] + sh[3];

    const float inv = 1.0f / sum;
    a.x *= inv; a.y *= inv; a.z *= inv; a.w *= inv;
    c.x *= inv; c.y *= inv; c.z *= inv; c.w *= inv;
    *(float4*)(p + t * 8) = a;
    *(float4*)(p + t * 8 + 4) = c;
}

// ============================================================================
// kernel_launch
// ============================================================================
extern "C" void kernel_launch(void* const* d_in, const int* in_sizes, int n_in,
                              void* d_out, int out_size)
{
    (void)in_sizes; (void)n_in; (void)out_size;

    const float* q   = (const float*)d_in[0];
    const float* k   = (const float*)d_in[1];
    const float* v   = (const float*)d_in[2];
    const float* Wq  = (const float*)d_in[3];
    const float* bq  = (const float*)d_in[4];
    const float* Wk  = (const float*)d_in[5];
    const float* bk  = (const float*)d_in[6];
    const float* Wv  = (const float*)d_in[7];
    const float* bv  = (const float*)d_in[8];
    const float* Uq  = (const float*)d_in[9];
    const float* buq = (const float*)d_in[10];
    const float* Uk  = (const float*)d_in[11];
    const float* buk = (const float*)d_in[12];
    const float* pt  = (const float*)d_in[13];
    const float* tcc = (const float*)d_in[14];
    const float* tco = (const float*)d_in[15];
    const float* toc = (const float*)d_in[16];
    const float* Wo  = (const float*)d_in[17];
    const float* bo  = (const float*)d_in[18];
    float* out = (float*)d_out;

    float *qc, *kc, *vc, *qp, *kp, *pos, *scores, *ctx, *wt, *vt;
    cudaGetSymbolAddress((void**)&qc, g_qc);
    cudaGetSymbolAddress((void**)&kc, g_kc);
    cudaGetSymbolAddress((void**)&vc, g_vc);
    cudaGetSymbolAddress((void**)&qp, g_qp);
    cudaGetSymbolAddress((void**)&kp, g_kp);
    cudaGetSymbolAddress((void**)&pos, g_pos);
    cudaGetSymbolAddress((void**)&scores, g_scores);
    cudaGetSymbolAddress((void**)&ctx, g_ctx);
    cudaGetSymbolAddress((void**)&wt, g_wt);
    cudaGetSymbolAddress((void**)&vt, g_vt);

    const size_t WSZ = (size_t)D_MODEL * D_MODEL;
    const dim3 tgrid(32, 32), tblk(32, 8);

    // transpose weights once (Wt layout: [N][K])
    transpose1024<<<tgrid, tblk>>>(Wq, wt + 0 * WSZ);
    transpose1024<<<tgrid, tblk>>>(Wk, wt + 1 * WSZ);
    transpose1024<<<tgrid, tblk>>>(Wv, wt + 2 * WSZ);
    transpose1024<<<tgrid, tblk>>>(Uq, wt + 3 * WSZ);
    transpose1024<<<tgrid, tblk>>>(Uk, wt + 4 * WSZ);
    transpose1024<<<tgrid, tblk>>>(Wo, wt + 5 * WSZ);

    // projections (bf16x3 mma.sync, fp32-grade)
    proj_mma<<<dim3(8, 32), 256>>>(q, wt + 0 * WSZ, bq, qc);
    proj_mma<<<dim3(8, 32), 256>>>(k, wt + 1 * WSZ, bk, kc);
    proj_mma<<<dim3(8, 32), 256>>>(v, wt + 2 * WSZ, bv, vc);
    proj_mma<<<dim3(8, 8), 256>>>(pt, wt + 3 * WSZ, buq, qp);
    proj_mma<<<dim3(8, 8), 256>>>(pt, wt + 4 * WSZ, buk, kp);

    // V^T per head for the AV GEMM
    transpose_v<<<dim3(S_ / 32, DEPTH / 32, B_ * NUM_HEADS), tblk>>>(vc, vt);

    // pos scores (theta patches fused)
    pos_mma<<<dim3(8, 8, NUM_HEADS), 256>>>(qp, kp, tcc, tco, toc, pos);

    // content scores + pos + scale
    content_mma<<<dim3(8, 8, B_ * NUM_HEADS), 256>>>(qc, kc, pos, scores);

    // softmax (in place)
    softmax_kernel<<<B_ * NUM_HEADS * S_, 128>>>(scores);

    // attn @ V
    av_mma<<<dim3(1, 8, B_ * NUM_HEADS), 256>>>(scores, vt, ctx);

    // output projection
    proj_mma<<<dim3(8, 32), 256>>>(ctx, wt + 5 * WSZ, bo, out);
}